// round 3
// baseline (speedup 1.0000x reference)
#include <cuda_runtime.h>

// ---------------------------------------------------------------------------
// MultiAgentCommSystem — fully fused, one CTA per batch (4096 CTAs x 256 thr)
//
// Pipeline per batch b (N=64 agents), entirely in 128KB shared memory:
//   1. load obs[b]            (64x128)                       -> s_obs
//   2. h   = relu(obs@W1+b1)  (64x128, K=128)                -> s_big
//   3. msg = h@W2+b2          (64x64,  K=128)                -> s_c  (+gmem)
//   4. qkv = msg@Wqkv+b       (64x192, K=64)                 -> s_big
//   5. attention (H=4, HD=16), softmax over 64 keys          -> s_c
//   6. agg = ctx@Wo+bo        (64x64,  K=64)                 -> s_d
//   7. z   = [obs,agg]@Wi1+b  (64x256, K=192)                -> s_big
//   8. LayerNorm(256) + ReLU in place
//   9. out = z@Wi2+b          (64x128, K=256)                -> gmem
//
// All GEMM inner loops use packed fp32x2 FMA (fma.rn.f32x2) — exact fp32
// arithmetic at 2x issue density on sm_103a.
// ---------------------------------------------------------------------------

typedef unsigned long long ull;
#define DEV __device__ __forceinline__

DEV ull pack2(float x) {
    ull r; asm("mov.b64 %0, {%1, %1};" : "=l"(r) : "f"(x)); return r;
}
DEV void fma2(ull& acc, ull a, ull w) {
    asm("fma.rn.f32x2 %0, %1, %2, %0;" : "+l"(acc) : "l"(a), "l"(w));
}
DEV float2 unpack2(ull v) {
    float2 f; asm("mov.b64 {%0, %1}, %2;" : "=f"(f.x), "=f"(f.y) : "l"(v)); return f;
}

// C[64][NC] = act(A[64][K] @ W[K][NC] + bias); A in smem, W in gmem (L2-hot).
// Thread map: 16 row-groups x 16 col-groups; 4 rows x (NC/16) cols per thread.
template<int K, int NC, int LDA, int LDC, bool RELU>
DEV void gemm_smem(const float* __restrict__ sA, const float* __restrict__ W,
                   const float* __restrict__ bias, float* __restrict__ sC, int tid)
{
    constexpr int CPT = NC / 16;   // cols per thread (always even)
    constexpr int NP  = CPT / 2;   // packed f32x2 pairs
    const int r0 = (tid >> 4) << 2;
    const int c0 = (tid & 15) * CPT;

    ull acc[4][NP];
    #pragma unroll
    for (int i = 0; i < 4; i++)
        #pragma unroll
        for (int j = 0; j < NP; j++) acc[i][j] = 0ull;

    const float* Wc = W + c0;
    #pragma unroll 4
    for (int k = 0; k < K; k++) {
        const ull* wr = (const ull*)(Wc + k * NC);
        ull w2[NP];
        #pragma unroll
        for (int j = 0; j < NP; j++) w2[j] = wr[j];
        #pragma unroll
        for (int i = 0; i < 4; i++) {
            ull a2 = pack2(sA[(r0 + i) * LDA + k]);   // 16-lane smem broadcast
            #pragma unroll
            for (int j = 0; j < NP; j++) fma2(acc[i][j], a2, w2[j]);
        }
    }
    #pragma unroll
    for (int i = 0; i < 4; i++) {
        #pragma unroll
        for (int j = 0; j < NP; j++) {
            float2 v = unpack2(acc[i][j]);
            v.x += bias[c0 + 2 * j];
            v.y += bias[c0 + 2 * j + 1];
            if (RELU) { v.x = fmaxf(v.x, 0.f); v.y = fmaxf(v.y, 0.f); }
            *(float2*)(sC + (r0 + i) * LDC + c0 + 2 * j) = v;
        }
    }
}

// z[64][256] = [obs(128) | agg(64)] @ Wi1[192][256] + b  (concat GEMM, K split)
DEV void gemm_integrate(const float* __restrict__ sObs, const float* __restrict__ sAgg,
                        const float* __restrict__ W, const float* __restrict__ bias,
                        float* __restrict__ sZ, int tid)
{
    constexpr int NC = 256, CPT = 16, NP = 8;
    const int r0 = (tid >> 4) << 2;
    const int c0 = (tid & 15) * CPT;

    ull acc[4][NP];
    #pragma unroll
    for (int i = 0; i < 4; i++)
        #pragma unroll
        for (int j = 0; j < NP; j++) acc[i][j] = 0ull;

    const float* Wc = W + c0;
    #pragma unroll 4
    for (int k = 0; k < 128; k++) {
        const ull* wr = (const ull*)(Wc + k * NC);
        ull w2[NP];
        #pragma unroll
        for (int j = 0; j < NP; j++) w2[j] = wr[j];
        #pragma unroll
        for (int i = 0; i < 4; i++) {
            ull a2 = pack2(sObs[(r0 + i) * 128 + k]);
            #pragma unroll
            for (int j = 0; j < NP; j++) fma2(acc[i][j], a2, w2[j]);
        }
    }
    #pragma unroll 4
    for (int k = 0; k < 64; k++) {
        const ull* wr = (const ull*)(Wc + (128 + k) * NC);
        ull w2[NP];
        #pragma unroll
        for (int j = 0; j < NP; j++) w2[j] = wr[j];
        #pragma unroll
        for (int i = 0; i < 4; i++) {
            ull a2 = pack2(sAgg[(r0 + i) * 64 + k]);
            #pragma unroll
            for (int j = 0; j < NP; j++) fma2(acc[i][j], a2, w2[j]);
        }
    }
    #pragma unroll
    for (int i = 0; i < 4; i++) {
        #pragma unroll
        for (int j = 0; j < NP; j++) {
            float2 v = unpack2(acc[i][j]);
            v.x += bias[c0 + 2 * j];
            v.y += bias[c0 + 2 * j + 1];
            *(float2*)(sZ + (r0 + i) * 256 + c0 + 2 * j) = v;
        }
    }
}

// out[64][128] = relu'd-z[64][256] @ Wi2[256][128] + b  -> gmem (enriched)
DEV void gemm_final(const float* __restrict__ sZ, const float* __restrict__ W,
                    const float* __restrict__ bias, float* __restrict__ gOut, int tid)
{
    constexpr int NC = 128, CPT = 8, NP = 4;
    const int r0 = (tid >> 4) << 2;
    const int c0 = (tid & 15) * CPT;

    ull acc[4][NP];
    #pragma unroll
    for (int i = 0; i < 4; i++)
        #pragma unroll
        for (int j = 0; j < NP; j++) acc[i][j] = 0ull;

    const float* Wc = W + c0;
    #pragma unroll 4
    for (int k = 0; k < 256; k++) {
        const ull* wr = (const ull*)(Wc + k * NC);
        ull w2[NP];
        #pragma unroll
        for (int j = 0; j < NP; j++) w2[j] = wr[j];
        #pragma unroll
        for (int i = 0; i < 4; i++) {
            ull a2 = pack2(sZ[(r0 + i) * 256 + k]);
            #pragma unroll
            for (int j = 0; j < NP; j++) fma2(acc[i][j], a2, w2[j]);
        }
    }
    #pragma unroll
    for (int i = 0; i < 4; i++) {
        #pragma unroll
        for (int j = 0; j < NP; j++) {
            float2 v = unpack2(acc[i][j]);
            v.x += bias[c0 + 2 * j];
            v.y += bias[c0 + 2 * j + 1];
            *(float2*)(gOut + (r0 + i) * 128 + c0 + 2 * j) = v;
        }
    }
}

// 4 heads, HD=16, 64 keys. One warp = one (head, 32-q-row block). Scores kept
// fully in registers; softmax scale folded into q.
DEV void attention(const float* __restrict__ sQKV /*64x192*/,
                   float* __restrict__ sCtx /*64x64*/, int tid)
{
    const int warp = tid >> 5;
    const int lane = tid & 31;
    const int head = warp >> 1;
    const int qrow = ((warp & 1) << 5) + lane;

    const float* qp = sQKV + qrow * 192 + head * 16;
    float q[16];
    #pragma unroll
    for (int d = 0; d < 16; d++) q[d] = qp[d] * 0.25f;   // 1/sqrt(16)

    float s[64];
    #pragma unroll
    for (int j = 0; j < 64; j++) {
        const float4* kp = (const float4*)(sQKV + j * 192 + 64 + head * 16);
        float a = 0.f;
        #pragma unroll
        for (int t = 0; t < 4; t++) {
            float4 kv = kp[t];  // broadcast: all lanes same address
            a += q[4*t+0]*kv.x + q[4*t+1]*kv.y + q[4*t+2]*kv.z + q[4*t+3]*kv.w;
        }
        s[j] = a;
    }
    float m = s[0];
    #pragma unroll
    for (int j = 1; j < 64; j++) m = fmaxf(m, s[j]);
    float sum = 0.f;
    #pragma unroll
    for (int j = 0; j < 64; j++) { s[j] = __expf(s[j] - m); sum += s[j]; }
    const float inv = 1.f / sum;

    float acc[16];
    #pragma unroll
    for (int d = 0; d < 16; d++) acc[d] = 0.f;
    #pragma unroll
    for (int j = 0; j < 64; j++) {
        const float4* vp = (const float4*)(sQKV + j * 192 + 128 + head * 16);
        float p = s[j];
        #pragma unroll
        for (int t = 0; t < 4; t++) {
            float4 vv = vp[t];
            acc[4*t+0] += p * vv.x; acc[4*t+1] += p * vv.y;
            acc[4*t+2] += p * vv.z; acc[4*t+3] += p * vv.w;
        }
    }
    float* cp = sCtx + qrow * 64 + head * 16;
    #pragma unroll
    for (int d = 0; d < 16; d++) cp[d] = acc[d] * inv;
}

DEV void layernorm_relu(float* __restrict__ sZ /*64x256*/,
                        const float* __restrict__ g, const float* __restrict__ b, int tid)
{
    const int warp = tid >> 5, lane = tid & 31;
    for (int row = warp; row < 64; row += 8) {
        float* zp = sZ + row * 256;
        float v[8], sum = 0.f, sq = 0.f;
        #pragma unroll
        for (int t = 0; t < 8; t++) {
            v[t] = zp[lane + 32 * t];
            sum += v[t]; sq += v[t] * v[t];
        }
        #pragma unroll
        for (int o = 16; o > 0; o >>= 1) {
            sum += __shfl_xor_sync(0xffffffffu, sum, o);
            sq  += __shfl_xor_sync(0xffffffffu, sq, o);
        }
        const float mu  = sum * (1.f / 256.f);
        const float var = sq * (1.f / 256.f) - mu * mu;
        const float rs  = rsqrtf(var + 1e-5f);
        #pragma unroll
        for (int t = 0; t < 8; t++) {
            const int c = lane + 32 * t;
            float y = (v[t] - mu) * rs * g[c] + b[c];
            zp[c] = fmaxf(y, 0.f);
        }
    }
}

__global__ void __launch_bounds__(256, 1)
comm_kernel(const float* __restrict__ obs,
            const float* __restrict__ enc_w1, const float* __restrict__ enc_b1,
            const float* __restrict__ enc_w2, const float* __restrict__ enc_b2,
            const float* __restrict__ in_proj_w, const float* __restrict__ in_proj_b,
            const float* __restrict__ out_w, const float* __restrict__ out_b,
            const float* __restrict__ int_w1, const float* __restrict__ int_b1,
            const float* __restrict__ ln_g, const float* __restrict__ ln_b,
            const float* __restrict__ int_w2, const float* __restrict__ int_b2,
            float* __restrict__ out_enriched, float* __restrict__ out_msgs)
{
    extern __shared__ float smem[];
    float* s_obs = smem;              // 64*128 = 8192 floats
    float* s_big = smem + 8192;       // 64*256 = 16384 floats (h / qkv / z)
    float* s_c   = smem + 24576;      // 64*64  = 4096 floats  (msgs / ctx)
    float* s_d   = smem + 28672;      // 64*64  = 4096 floats  (agg)

    const int b   = blockIdx.x;
    const int tid = threadIdx.x;

    // load obs tile: 8192 floats = 2048 float4, 8 per thread
    {
        const float4* g = (const float4*)(obs + (size_t)b * 8192);
        float4* sd = (float4*)s_obs;
        #pragma unroll
        for (int i = 0; i < 8; i++) sd[tid + i * 256] = g[tid + i * 256];
    }
    __syncthreads();

    // 1) h = relu(obs @ enc_w1 + b1)
    gemm_smem<128, 128, 128, 128, true>(s_obs, enc_w1, enc_b1, s_big, tid);
    __syncthreads();

    // 2) msgs = h @ enc_w2 + b2
    gemm_smem<128, 64, 128, 64, false>(s_big, enc_w2, enc_b2, s_c, tid);
    __syncthreads();

    // write msgs output (second tuple element)
    {
        float4* g = (float4*)(out_msgs + (size_t)b * 4096);
        const float4* sd = (const float4*)s_c;
        #pragma unroll
        for (int i = 0; i < 4; i++) g[tid + i * 256] = sd[tid + i * 256];
    }

    // 3) qkv = msgs @ in_proj_w + b
    gemm_smem<64, 192, 64, 192, false>(s_c, in_proj_w, in_proj_b, s_big, tid);
    __syncthreads();

    // 4) attention -> ctx (overwrites msgs, no longer needed)
    attention(s_big, s_c, tid);
    __syncthreads();

    // 5) agg = ctx @ out_w + b
    gemm_smem<64, 64, 64, 64, false>(s_c, out_w, out_b, s_d, tid);
    __syncthreads();

    // 6) z = [obs | agg] @ int_w1 + b (overwrites qkv)
    gemm_integrate(s_obs, s_d, int_w1, int_b1, s_big, tid);
    __syncthreads();

    // 7) LayerNorm + ReLU in place
    layernorm_relu(s_big, ln_g, ln_b, tid);
    __syncthreads();

    // 8) enriched = z @ int_w2 + b -> gmem
    gemm_final(s_big, int_w2, int_b2, out_enriched + (size_t)b * 8192, tid);
}

extern "C" void kernel_launch(void* const* d_in, const int* in_sizes, int n_in,
                              void* d_out, int out_size)
{
    const float* obs       = (const float*)d_in[0];
    const float* enc_w1    = (const float*)d_in[1];
    const float* enc_b1    = (const float*)d_in[2];
    const float* enc_w2    = (const float*)d_in[3];
    const float* enc_b2    = (const float*)d_in[4];
    const float* in_proj_w = (const float*)d_in[5];
    const float* in_proj_b = (const float*)d_in[6];
    const float* out_w     = (const float*)d_in[7];
    const float* out_b     = (const float*)d_in[8];
    const float* int_w1    = (const float*)d_in[9];
    const float* int_b1    = (const float*)d_in[10];
    const float* ln_g      = (const float*)d_in[11];
    const float* ln_b      = (const float*)d_in[12];
    const float* int_w2    = (const float*)d_in[13];
    const float* int_b2    = (const float*)d_in[14];

    float* out_enriched = (float*)d_out;                       // (B,N,128)
    float* out_msgs     = (float*)d_out + (size_t)4096 * 64 * 128;  // (B,N,64)

    const int smem_bytes = 32768 * sizeof(float);  // 131072
    cudaFuncSetAttribute(comm_kernel, cudaFuncAttributeMaxDynamicSharedMemorySize, smem_bytes);

    comm_kernel<<<4096, 256, smem_bytes>>>(
        obs, enc_w1, enc_b1, enc_w2, enc_b2,
        in_proj_w, in_proj_b, out_w, out_b,
        int_w1, int_b1, ln_g, ln_b, int_w2, int_b2,
        out_enriched, out_msgs);
}